// round 11
// baseline (speedup 1.0000x reference)
#include <cuda_runtime.h>
#include <cuda_fp16.h>
#include <cstdint>
#include <math.h>

#define B_ 4
#define S_ 1024
#define D_ 1024
#define F_ 4096
#define E_ 8
#define K_ 2
#define T_ (B_*S_)      // 4096 tokens
#define P_ (T_*K_)      // 8192 token-expert pairs

// ---------------- device scratch ------------------------------------------
__device__ float g_logits[T_*E_];
__device__ int   g_topi[T_*K_];
__device__ float g_topw[T_*K_];
__device__ int   g_counts[E_];
__device__ int   g_offsets[E_];
__device__ int   g_cursor[E_];
__device__ int   g_pair_token[P_];
__device__ float g_pair_w[P_];

__device__ __half g_x16[(size_t)T_*D_];
__device__ __half g_w1_16[(size_t)E_*D_*F_];
__device__ __half g_w3_16[(size_t)E_*D_*F_];
__device__ __half g_w2_16[(size_t)E_*F_*D_];
__device__ __half g_h16[(size_t)P_*F_];

// ---------------- helpers --------------------------------------------------
__device__ __forceinline__ uint32_t smem_u32(const void* p) {
    uint32_t a;
    asm("{ .reg .u64 t; cvta.to.shared.u64 t, %1; cvt.u32.u64 %0, t; }"
        : "=r"(a) : "l"(p));
    return a;
}

#define LDSM4(R, addr) \
    asm volatile("ldmatrix.sync.aligned.m8n8.x4.shared.b16 {%0,%1,%2,%3}, [%4];" \
        : "=r"((R)[0]), "=r"((R)[1]), "=r"((R)[2]), "=r"((R)[3]) : "r"(addr))

#define LDSM4T(R, addr) \
    asm volatile("ldmatrix.sync.aligned.m8n8.x4.trans.shared.b16 {%0,%1,%2,%3}, [%4];" \
        : "=r"((R)[0]), "=r"((R)[1]), "=r"((R)[2]), "=r"((R)[3]) : "r"(addr))

#define MMA(D, A, B0, B1) \
    asm volatile("mma.sync.aligned.m16n8k16.row.col.f32.f16.f16.f32 " \
        "{%0,%1,%2,%3},{%4,%5,%6,%7},{%8,%9},{%0,%1,%2,%3};" \
        : "+f"((D)[0]), "+f"((D)[1]), "+f"((D)[2]), "+f"((D)[3]) \
        : "r"((A)[0]), "r"((A)[1]), "r"((A)[2]), "r"((A)[3]), "r"(B0), "r"(B1))

#define CP16(dst, src) \
    asm volatile("cp.async.cg.shared.global [%0], [%1], 16;" :: "r"(dst), "l"(src))
#define CP_COMMIT() asm volatile("cp.async.commit_group;" ::: "memory")
#define CP_WAIT2()  asm volatile("cp.async.wait_group 2;" ::: "memory")

__device__ __forceinline__ uint32_t hpack(__half2 h) {
    return *reinterpret_cast<uint32_t*>(&h);
}

// ---------------- router (+x16 convert, +init) ------------------------------
__global__ void router_kernel(const float* __restrict__ x,
                              const float* __restrict__ gw) {
    int t = blockIdx.x;
    if (t == 0 && threadIdx.x < E_) {
        g_counts[threadIdx.x] = 0;
        g_cursor[threadIdx.x] = 0;
    }
    const float* xr = x + (size_t)t * D_;
    __half* xo = g_x16 + (size_t)t * D_;
    float acc[E_];
#pragma unroll
    for (int e = 0; e < E_; e++) acc[e] = 0.f;
    for (int d = threadIdx.x; d < D_; d += blockDim.x) {
        float xv = xr[d];
        xo[d] = __float2half_rn(xv);
#pragma unroll
        for (int e = 0; e < E_; e++) acc[e] = fmaf(xv, gw[e * D_ + d], acc[e]);
    }
#pragma unroll
    for (int e = 0; e < E_; e++)
        for (int o = 16; o > 0; o >>= 1)
            acc[e] += __shfl_down_sync(0xffffffffu, acc[e], o);
    __shared__ float s[4][E_];
    int warp = threadIdx.x >> 5, lane = threadIdx.x & 31;
    if (lane == 0) {
#pragma unroll
        for (int e = 0; e < E_; e++) s[warp][e] = acc[e];
    }
    __syncthreads();
    if (threadIdx.x < E_) {
        g_logits[t * E_ + threadIdx.x] =
            s[0][threadIdx.x] + s[1][threadIdx.x] + s[2][threadIdx.x] + s[3][threadIdx.x];
    }
}

// ---------------- topk (+rl reduction) --------------------------------------
__global__ void topk_kernel(float* __restrict__ out_rl) {
    int t = blockIdx.x * blockDim.x + threadIdx.x;   // blockDim = 256
    float l[E_];
#pragma unroll
    for (int e = 0; e < E_; e++) l[e] = g_logits[t * E_ + e];
    int i0 = 0; float m0 = l[0];
#pragma unroll
    for (int e = 1; e < E_; e++) if (l[e] > m0) { m0 = l[e]; i0 = e; }
    int i1 = -1; float m1 = -1e30f;
#pragma unroll
    for (int e = 0; e < E_; e++) if (e != i0 && l[e] > m1) { m1 = l[e]; i1 = e; }
    float e1  = expf(m1 - m0);
    float inv = 1.f / (1.f + e1);
    g_topi[t * 2 + 0] = i0; g_topw[t * 2 + 0] = inv;
    g_topi[t * 2 + 1] = i1; g_topw[t * 2 + 1] = e1 * inv;
    atomicAdd(&g_counts[i0], 1);
    atomicAdd(&g_counts[i1], 1);

    __shared__ float sm[8][E_];
    int warp = threadIdx.x >> 5, lane = threadIdx.x & 31;
#pragma unroll
    for (int e = 0; e < E_; e++) {
        float v = l[e];
        for (int o = 16; o > 0; o >>= 1)
            v += __shfl_down_sync(0xffffffffu, v, o);
        if (lane == 0) sm[warp][e] = v;
    }
    __syncthreads();
    if (threadIdx.x < E_) {
        float v = 0.f;
#pragma unroll
        for (int w = 0; w < 8; w++) v += sm[w][threadIdx.x];
        int b = blockIdx.x >> 2;
        atomicAdd(&out_rl[b * E_ + threadIdx.x], v * (1.f / S_));
    }
}

__global__ void offsets_kernel() {
    if (threadIdx.x == 0) {
        int acc = 0;
        for (int e = 0; e < E_; e++) { g_offsets[e] = acc; acc += g_counts[e]; }
    }
}

__global__ void scatter_kernel() {
    int t = blockIdx.x * blockDim.x + threadIdx.x;
    if (t >= T_) return;
#pragma unroll
    for (int k = 0; k < K_; k++) {
        int e = g_topi[t * 2 + k];
        int p = g_offsets[e] + atomicAdd(&g_cursor[e], 1);
        g_pair_token[p] = t;
        g_pair_w[p]     = g_topw[t * 2 + k];
    }
}

// ---------------- fp32 -> fp16 converts -------------------------------------
__global__ void tofp16_kernel(const float* __restrict__ src,
                              __half* __restrict__ dst, size_t n4) {
    size_t stride = (size_t)gridDim.x * blockDim.x;
    for (size_t i = (size_t)blockIdx.x * blockDim.x + threadIdx.x; i < n4; i += stride) {
        float4 v = ((const float4*)src)[i];
        uint2 o;
        o.x = hpack(__floats2half2_rn(v.x, v.y));
        o.y = hpack(__floats2half2_rn(v.z, v.w));
        ((uint2*)dst)[i] = o;
    }
}

// dual convert: blockIdx.y selects (w1, w3)
__global__ void tofp16_dual_kernel(const float* __restrict__ s0, __half* __restrict__ d0,
                                   const float* __restrict__ s1, __half* __restrict__ d1,
                                   size_t n4) {
    const float* src = blockIdx.y ? s1 : s0;
    __half* dst      = blockIdx.y ? d1 : d0;
    size_t stride = (size_t)gridDim.x * blockDim.x;
    for (size_t i = (size_t)blockIdx.x * blockDim.x + threadIdx.x; i < n4; i += stride) {
        float4 v = ((const float4*)src)[i];
        uint2 o;
        o.x = hpack(__floats2half2_rn(v.x, v.y));
        o.y = hpack(__floats2half2_rn(v.z, v.w));
        ((uint2*)dst)[i] = o;
    }
}

// ---------------- mma.sync GEMMs, fp16, K-chunk=32, 4-stage ------------------
#define A_STRIDE 80            // 32 fp16 (64B) + 16B pad; 5x16B -> conflict-free
#define B_STRIDE 272           // 128 fp16 (256B) + 16B pad
#define A_T 10240              // 128*80
#define B_T 8704               // 32*272
#define G1_ST (A_T + 2*B_T)    // 27648
#define G2_ST (A_T + B_T)      // 18944
#define NSTG 4
#define G1_SMEM (NSTG*G1_ST)   // 110592 -> 2 CTAs/SM
#define G2_SMEM (NSTG*G2_ST)   // 75776  -> 2 CTAs/SM
#define NCH1 (D_/32)           // 32
#define NCH2H (F_/2/32)        // 64 per split-K half

__device__ __forceinline__ float silu(float g) {
    return g / (1.f + expf(-g));
}

// GEMM1: h = silu(xg @ w1) * (xg @ w3)  (M=128 pairs, N=128 of F, K=D)
// 512 threads, 4x4 warps of 32x32 warp tiles. ebase selects expert group.
__global__ __launch_bounds__(512)
void gemm1_mma(int ebase) {
    extern __shared__ char smem[];
    int e = ebase + blockIdx.z;
    int cnt = g_counts[e];
    int m0 = blockIdx.x * 128;
    if (m0 >= cnt) return;
    int base = g_offsets[e];
    int n0 = blockIdx.y * 128;

    int tid = threadIdx.x;
    uint32_t sb = smem_u32(smem);

    int arow = tid >> 2, aq = tid & 3;
    int rcl = min(m0 + arow, cnt - 1);
    int tok = g_pair_token[base + rcl];
    const __half* asrc = g_x16 + (size_t)tok * D_ + aq * 8;
    uint32_t adst = (uint32_t)(arow * A_STRIDE + aq * 16);

    const __half* bsrc[2];
    uint32_t bdst[2];
#pragma unroll
    for (int i = 0; i < 2; i++) {
        int idx = i * 512 + tid;
        int mat = idx >> 9, rem = idx & 511;
        int krow = rem >> 4, col = rem & 15;
        bsrc[i] = (mat ? g_w3_16 : g_w1_16) + (size_t)e * D_ * F_
                  + (size_t)krow * F_ + n0 + col * 8;
        bdst[i] = (uint32_t)(A_T + mat * B_T + krow * B_STRIDE + col * 16);
    }

    auto issue = [&](int c, int slot) {
        uint32_t st = sb + slot * G1_ST;
        CP16(st + adst, asrc + c * 32);
#pragma unroll
        for (int i = 0; i < 2; i++)
            CP16(st + bdst[i], bsrc[i] + (size_t)c * 32 * F_);
    };

    int wid = tid >> 5, lane = tid & 31;
    int wm = wid & 3, wn = wid >> 2;
    int la_row = (lane & 7) + ((lane >> 3) & 1) * 8;
    int la_k   = (lane >> 4) * 8;
    uint32_t aoff = (uint32_t)((wm * 32 + la_row) * A_STRIDE + la_k * 2);
    int lb_k = (lane & 7) + ((lane >> 3) & 1) * 8;
    int lb_n = (lane >> 4) * 8;
    uint32_t boff = (uint32_t)(lb_k * B_STRIDE + (wn * 32 + lb_n) * 2);

    float acc1[2][4][4], acc3[2][4][4];
#pragma unroll
    for (int mt = 0; mt < 2; mt++)
#pragma unroll
        for (int nt = 0; nt < 4; nt++)
#pragma unroll
            for (int c = 0; c < 4; c++) { acc1[mt][nt][c] = 0.f; acc3[mt][nt][c] = 0.f; }

    auto compute = [&](int slot) {
        uint32_t stb = sb + slot * G1_ST;
#pragma unroll
        for (int ks = 0; ks < 2; ks++) {
            uint32_t Ah = stb + aoff + ks * 32;
            uint32_t Bb = stb + A_T + boff + ks * 16 * B_STRIDE;
            uint32_t a[2][4];
            LDSM4(a[0], Ah);
            LDSM4(a[1], Ah + 16 * A_STRIDE);
#pragma unroll
            for (int ng = 0; ng < 2; ng++) {
                uint32_t b1[4], b3[4];
                LDSM4T(b1, Bb + ng * 32);
                LDSM4T(b3, Bb + B_T + ng * 32);
#pragma unroll
                for (int mt = 0; mt < 2; mt++)
#pragma unroll
                    for (int j = 0; j < 2; j++) {
                        int nt = ng * 2 + j;
                        MMA(acc1[mt][nt], a[mt], b1[2 * j], b1[2 * j + 1]);
                        MMA(acc3[mt][nt], a[mt], b3[2 * j], b3[2 * j + 1]);
                    }
            }
        }
    };

#pragma unroll
    for (int s = 0; s < NSTG - 1; s++) { issue(s, s); CP_COMMIT(); }
#pragma unroll 1
    for (int c = 0; c < NCH1; c++) {
        CP_WAIT2();
        __syncthreads();
        int nc = c + NSTG - 1;
        if (nc < NCH1) issue(nc, nc & (NSTG - 1));
        CP_COMMIT();
        compute(c & (NSTG - 1));
    }

    int r0  = m0 + wm * 32 + (lane >> 2);
    int col = n0 + wn * 32 + (lane & 3) * 2;
#pragma unroll
    for (int mt = 0; mt < 2; mt++) {
#pragma unroll
        for (int half = 0; half < 2; half++) {
            int ra = r0 + mt * 16 + half * 8;
            if (ra < cnt) {
                size_t rowo = (size_t)(base + ra) * F_;
#pragma unroll
                for (int nt = 0; nt < 4; nt++) {
                    int cc = col + nt * 8;
                    float vx = silu(acc1[mt][nt][2 * half])     * acc3[mt][nt][2 * half];
                    float vy = silu(acc1[mt][nt][2 * half + 1]) * acc3[mt][nt][2 * half + 1];
                    *(uint32_t*)(g_h16 + rowo + cc) = hpack(__floats2half2_rn(vx, vy));
                }
            }
        }
    }
}

// GEMM2: out[token] += w * (h @ w2)  (M=128, N=128 of D, K=2048 per split half)
// 512 threads, 4x4 warps of 32x32 warp tiles (R9 config)
__global__ __launch_bounds__(512)
void gemm2_mma(float* __restrict__ out) {
    extern __shared__ char smem[];
    int e  = blockIdx.z >> 1;
    int kz = blockIdx.z & 1;
    int cnt = g_counts[e];
    int m0 = blockIdx.x * 128;
    if (m0 >= cnt) return;
    int base = g_offsets[e];
    int n0 = blockIdx.y * 128;
    int kbase = kz * (F_ / 2);

    int tid = threadIdx.x;
    uint32_t sb = smem_u32(smem);

    // A loader: 1 op/thread
    int arow = tid >> 2, aq = tid & 3;
    int rcl = min(m0 + arow, cnt - 1);
    const __half* asrc = g_h16 + (size_t)(base + rcl) * F_ + kbase + aq * 8;
    uint32_t adst = (uint32_t)(arow * A_STRIDE + aq * 16);

    // B loader: 1 op/thread: krow = tid>>4 (0..31), col = tid&15
    int bkrow = tid >> 4, bcol = tid & 15;
    const __half* bsrc = g_w2_16 + (size_t)e * F_ * D_
                         + (size_t)(kbase + bkrow) * D_ + n0 + bcol * 8;
    uint32_t bdst = (uint32_t)(A_T + bkrow * B_STRIDE + bcol * 16);

    auto issue = [&](int c, int slot) {
        uint32_t st = sb + slot * G2_ST;
        CP16(st + adst, asrc + c * 32);
        CP16(st + bdst, bsrc + (size_t)c * 32 * D_);
    };

    int wid = tid >> 5, lane = tid & 31;
    int wm = wid & 3, wn = wid >> 2;
    int la_row = (lane & 7) + ((lane >> 3) & 1) * 8;
    int la_k   = (lane >> 4) * 8;
    uint32_t aoff = (uint32_t)((wm * 32 + la_row) * A_STRIDE + la_k * 2);
    int lb_k = (lane & 7) + ((lane >> 3) & 1) * 8;
    int lb_n = (lane >> 4) * 8;
    uint32_t boff = (uint32_t)(lb_k * B_STRIDE + (wn * 32 + lb_n) * 2);

    float acc[2][4][4];
#pragma unroll
    for (int mt = 0; mt < 2; mt++)
#pragma unroll
        for (int nt = 0; nt < 4; nt++)
#pragma unroll
            for (int c = 0; c < 4; c++) acc[mt][nt][c] = 0.f;

    auto compute = [&](int slot) {
        uint32_t stb = sb + slot * G2_ST;
#pragma unroll
        for (int ks = 0; ks < 2; ks++) {
            uint32_t Ah = stb + aoff + ks * 32;
            uint32_t Bb = stb + A_T + boff + ks * 16 * B_STRIDE;
            uint32_t a[2][4];
            LDSM4(a[0], Ah);
            LDSM4(a[1], Ah + 16 * A_STRIDE);
#pragma unroll
            for (int ng = 0; ng < 2; ng++) {
                uint32_t b[4];
                LDSM4T(b, Bb + ng * 32);
#pragma unroll
                for (int mt = 0; mt < 2; mt++)
#pragma unroll
                    for (int j = 0; j < 2; j++) {
                        int nt = ng * 2 + j;
                        MMA(acc[mt][nt], a[mt], b[2 * j], b[2 * j + 1]);
                    }
            }
        }
    };

#pragma unroll
    for (int s = 0; s < NSTG - 1; s++) { issue(s, s); CP_COMMIT(); }
#pragma unroll 1
    for (int c = 0; c < NCH2H; c++) {
        CP_WAIT2();
        __syncthreads();
        int nc = c + NSTG - 1;
        if (nc < NCH2H) issue(nc, nc & (NSTG - 1));
        CP_COMMIT();
        compute(c & (NSTG - 1));
    }

    int r0  = m0 + wm * 32 + (lane >> 2);
    int col = n0 + wn * 32 + (lane & 3) * 2;
#pragma unroll
    for (int mt = 0; mt < 2; mt++) {
#pragma unroll
        for (int half = 0; half < 2; half++) {
            int ra = r0 + mt * 16 + half * 8;
            if (ra < cnt) {
                int p = base + ra;
                int tok = g_pair_token[p];
                float wgt = g_pair_w[p];
                float* op = out + (size_t)tok * D_;
#pragma unroll
                for (int nt = 0; nt < 4; nt++) {
                    int cc = col + nt * 8;
                    atomicAdd(op + cc,     acc[mt][nt][2 * half]     * wgt);
                    atomicAdd(op + cc + 1, acc[mt][nt][2 * half + 1] * wgt);
                }
            }
        }
    }
}

// ---------------- launch ---------------------------------------------------
static cudaStream_t g_s1 = nullptr, g_s2 = nullptr;
static cudaEvent_t  g_e0, g_e1a, g_e1b, g_e2;

extern "C" void kernel_launch(void* const* d_in, const int* in_sizes, int n_in,
                              void* d_out, int out_size) {
    const float* x  = (const float*)d_in[0];
    const float* gw = (const float*)d_in[1];
    const float* w1 = (const float*)d_in[2];
    const float* w3 = (const float*)d_in[3];
    const float* w2 = (const float*)d_in[4];
    float* out    = (float*)d_out;
    float* out_rl = out + (size_t)T_ * D_;

    if (g_s1 == nullptr) {
        cudaStreamCreateWithFlags(&g_s1, cudaStreamNonBlocking);
        cudaStreamCreateWithFlags(&g_s2, cudaStreamNonBlocking);
        cudaEventCreateWithFlags(&g_e0,  cudaEventDisableTiming);
        cudaEventCreateWithFlags(&g_e1a, cudaEventDisableTiming);
        cudaEventCreateWithFlags(&g_e1b, cudaEventDisableTiming);
        cudaEventCreateWithFlags(&g_e2,  cudaEventDisableTiming);
    }

    cudaFuncSetAttribute(gemm1_mma, cudaFuncAttributeMaxDynamicSharedMemorySize, G1_SMEM);
    cudaFuncSetAttribute(gemm2_mma, cudaFuncAttributeMaxDynamicSharedMemorySize, G2_SMEM);

    __half *w1_16, *w3_16, *w2_16;
    cudaGetSymbolAddress((void**)&w1_16, g_w1_16);
    cudaGetSymbolAddress((void**)&w3_16, g_w3_16);
    cudaGetSymbolAddress((void**)&w2_16, g_w2_16);

    const size_t HW = (size_t)(E_ / 2) * D_ * F_;   // elements in experts 0-3

    // fork converts onto side streams
    cudaEventRecord(g_e0, 0);
    cudaStreamWaitEvent(g_s1, g_e0, 0);
    cudaStreamWaitEvent(g_s2, g_e0, 0);
    // experts 0-3
    tofp16_dual_kernel<<<dim3(4096, 2), 256, 0, g_s1>>>(
        w1, w1_16, w3, w3_16, HW / 4);
    cudaEventRecord(g_e1a, g_s1);
    // experts 4-7
    tofp16_dual_kernel<<<dim3(4096, 2), 256, 0, g_s1>>>(
        w1 + HW, w1_16 + HW, w3 + HW, w3_16 + HW, HW / 4);
    cudaEventRecord(g_e1b, g_s1);
    tofp16_kernel<<<8192, 256, 0, g_s2>>>(w2, w2_16, (size_t)E_ * F_ * D_ / 4);
    cudaEventRecord(g_e2, g_s2);

    // main stream: routing chain
    cudaMemsetAsync(out, 0, (size_t)out_size * sizeof(float));
    router_kernel<<<T_, 128>>>(x, gw);
    topk_kernel<<<T_ / 256, 256>>>(out_rl);
    offsets_kernel<<<1, 32>>>();
    scatter_kernel<<<T_ / 256, 256>>>();

    // GEMM1 in two expert halves, each gated on its convert
    cudaStreamWaitEvent(0, g_e1a, 0);
    gemm1_mma<<<dim3(32, F_ / 128, E_ / 2), 512, G1_SMEM>>>(0);
    cudaStreamWaitEvent(0, g_e1b, 0);
    gemm1_mma<<<dim3(32, F_ / 128, E_ / 2), 512, G1_SMEM>>>(E_ / 2);

    cudaStreamWaitEvent(0, g_e2, 0);
    gemm2_mma<<<dim3(32, D_ / 128, E_ * 2), 512, G2_SMEM>>>(out);
}

// round 12
// speedup vs baseline: 1.0182x; 1.0182x over previous
#include <cuda_runtime.h>
#include <cuda_fp16.h>
#include <cstdint>
#include <math.h>

#define B_ 4
#define S_ 1024
#define D_ 1024
#define F_ 4096
#define E_ 8
#define K_ 2
#define T_ (B_*S_)      // 4096 tokens
#define P_ (T_*K_)      // 8192 token-expert pairs

// ---------------- device scratch ------------------------------------------
__device__ float g_logits[T_*E_];
__device__ int   g_topi[T_*K_];
__device__ float g_topw[T_*K_];
__device__ int   g_counts[E_];
__device__ int   g_offsets[E_];
__device__ int   g_cursor[E_];
__device__ int   g_pair_token[P_];
__device__ float g_pair_w[P_];

__device__ __half g_x16[(size_t)T_*D_];
__device__ __half g_w1_16[(size_t)E_*D_*F_];
__device__ __half g_w3_16[(size_t)E_*D_*F_];
__device__ __half g_w2_16[(size_t)E_*F_*D_];
__device__ __half g_h16[(size_t)P_*F_];

// ---------------- helpers --------------------------------------------------
__device__ __forceinline__ uint32_t smem_u32(const void* p) {
    uint32_t a;
    asm("{ .reg .u64 t; cvta.to.shared.u64 t, %1; cvt.u32.u64 %0, t; }"
        : "=r"(a) : "l"(p));
    return a;
}

#define LDSM4(R, addr) \
    asm volatile("ldmatrix.sync.aligned.m8n8.x4.shared.b16 {%0,%1,%2,%3}, [%4];" \
        : "=r"((R)[0]), "=r"((R)[1]), "=r"((R)[2]), "=r"((R)[3]) : "r"(addr))

#define LDSM4T(R, addr) \
    asm volatile("ldmatrix.sync.aligned.m8n8.x4.trans.shared.b16 {%0,%1,%2,%3}, [%4];" \
        : "=r"((R)[0]), "=r"((R)[1]), "=r"((R)[2]), "=r"((R)[3]) : "r"(addr))

#define MMA(D, A, B0, B1) \
    asm volatile("mma.sync.aligned.m16n8k16.row.col.f32.f16.f16.f32 " \
        "{%0,%1,%2,%3},{%4,%5,%6,%7},{%8,%9},{%0,%1,%2,%3};" \
        : "+f"((D)[0]), "+f"((D)[1]), "+f"((D)[2]), "+f"((D)[3]) \
        : "r"((A)[0]), "r"((A)[1]), "r"((A)[2]), "r"((A)[3]), "r"(B0), "r"(B1))

#define CP16(dst, src) \
    asm volatile("cp.async.cg.shared.global [%0], [%1], 16;" :: "r"(dst), "l"(src))
#define CP_COMMIT() asm volatile("cp.async.commit_group;" ::: "memory")
#define CP_WAIT2()  asm volatile("cp.async.wait_group 2;" ::: "memory")
#define CP_WAIT1()  asm volatile("cp.async.wait_group 1;" ::: "memory")

__device__ __forceinline__ uint32_t hpack(__half2 h) {
    return *reinterpret_cast<uint32_t*>(&h);
}

// ---------------- router (+x16 convert, +init) ------------------------------
__global__ void router_kernel(const float* __restrict__ x,
                              const float* __restrict__ gw) {
    int t = blockIdx.x;
    if (t == 0 && threadIdx.x < E_) {
        g_counts[threadIdx.x] = 0;
        g_cursor[threadIdx.x] = 0;
    }
    const float* xr = x + (size_t)t * D_;
    __half* xo = g_x16 + (size_t)t * D_;
    float acc[E_];
#pragma unroll
    for (int e = 0; e < E_; e++) acc[e] = 0.f;
    for (int d = threadIdx.x; d < D_; d += blockDim.x) {
        float xv = xr[d];
        xo[d] = __float2half_rn(xv);
#pragma unroll
        for (int e = 0; e < E_; e++) acc[e] = fmaf(xv, gw[e * D_ + d], acc[e]);
    }
#pragma unroll
    for (int e = 0; e < E_; e++)
        for (int o = 16; o > 0; o >>= 1)
            acc[e] += __shfl_down_sync(0xffffffffu, acc[e], o);
    __shared__ float s[4][E_];
    int warp = threadIdx.x >> 5, lane = threadIdx.x & 31;
    if (lane == 0) {
#pragma unroll
        for (int e = 0; e < E_; e++) s[warp][e] = acc[e];
    }
    __syncthreads();
    if (threadIdx.x < E_) {
        g_logits[t * E_ + threadIdx.x] =
            s[0][threadIdx.x] + s[1][threadIdx.x] + s[2][threadIdx.x] + s[3][threadIdx.x];
    }
}

// ---------------- topk (+rl reduction) --------------------------------------
__global__ void topk_kernel(float* __restrict__ out_rl) {
    int t = blockIdx.x * blockDim.x + threadIdx.x;   // blockDim = 256
    float l[E_];
#pragma unroll
    for (int e = 0; e < E_; e++) l[e] = g_logits[t * E_ + e];
    int i0 = 0; float m0 = l[0];
#pragma unroll
    for (int e = 1; e < E_; e++) if (l[e] > m0) { m0 = l[e]; i0 = e; }
    int i1 = -1; float m1 = -1e30f;
#pragma unroll
    for (int e = 0; e < E_; e++) if (e != i0 && l[e] > m1) { m1 = l[e]; i1 = e; }
    float e1  = expf(m1 - m0);
    float inv = 1.f / (1.f + e1);
    g_topi[t * 2 + 0] = i0; g_topw[t * 2 + 0] = inv;
    g_topi[t * 2 + 1] = i1; g_topw[t * 2 + 1] = e1 * inv;
    atomicAdd(&g_counts[i0], 1);
    atomicAdd(&g_counts[i1], 1);

    __shared__ float sm[8][E_];
    int warp = threadIdx.x >> 5, lane = threadIdx.x & 31;
#pragma unroll
    for (int e = 0; e < E_; e++) {
        float v = l[e];
        for (int o = 16; o > 0; o >>= 1)
            v += __shfl_down_sync(0xffffffffu, v, o);
        if (lane == 0) sm[warp][e] = v;
    }
    __syncthreads();
    if (threadIdx.x < E_) {
        float v = 0.f;
#pragma unroll
        for (int w = 0; w < 8; w++) v += sm[w][threadIdx.x];
        int b = blockIdx.x >> 2;
        atomicAdd(&out_rl[b * E_ + threadIdx.x], v * (1.f / S_));
    }
}

__global__ void offsets_kernel() {
    if (threadIdx.x == 0) {
        int acc = 0;
        for (int e = 0; e < E_; e++) { g_offsets[e] = acc; acc += g_counts[e]; }
    }
}

__global__ void scatter_kernel() {
    int t = blockIdx.x * blockDim.x + threadIdx.x;
    if (t >= T_) return;
#pragma unroll
    for (int k = 0; k < K_; k++) {
        int e = g_topi[t * 2 + k];
        int p = g_offsets[e] + atomicAdd(&g_cursor[e], 1);
        g_pair_token[p] = t;
        g_pair_w[p]     = g_topw[t * 2 + k];
    }
}

// ---------------- fp32 -> fp16 converts -------------------------------------
__global__ void tofp16_kernel(const float* __restrict__ src,
                              __half* __restrict__ dst, size_t n4) {
    size_t stride = (size_t)gridDim.x * blockDim.x;
    for (size_t i = (size_t)blockIdx.x * blockDim.x + threadIdx.x; i < n4; i += stride) {
        float4 v = ((const float4*)src)[i];
        uint2 o;
        o.x = hpack(__floats2half2_rn(v.x, v.y));
        o.y = hpack(__floats2half2_rn(v.z, v.w));
        ((uint2*)dst)[i] = o;
    }
}

// dual convert: blockIdx.y selects (w1, w3)
__global__ void tofp16_dual_kernel(const float* __restrict__ s0, __half* __restrict__ d0,
                                   const float* __restrict__ s1, __half* __restrict__ d1,
                                   size_t n4) {
    const float* src = blockIdx.y ? s1 : s0;
    __half* dst      = blockIdx.y ? d1 : d0;
    size_t stride = (size_t)gridDim.x * blockDim.x;
    for (size_t i = (size_t)blockIdx.x * blockDim.x + threadIdx.x; i < n4; i += stride) {
        float4 v = ((const float4*)src)[i];
        uint2 o;
        o.x = hpack(__floats2half2_rn(v.x, v.y));
        o.y = hpack(__floats2half2_rn(v.z, v.w));
        ((uint2*)dst)[i] = o;
    }
}

// ---------------- GEMM tile constants ---------------------------------------
// GEMM1 (K-chunk 32, 4 stages, R9 config)
#define A_STRIDE 80            // 32 fp16 (64B) + 16B pad
#define B_STRIDE 272           // 128 fp16 (256B) + 16B pad
#define A_T 10240              // 128*80
#define B_T 8704               // 32*272
#define G1_ST (A_T + 2*B_T)    // 27648
#define NSTG 4
#define G1_SMEM (NSTG*G1_ST)   // 110592 -> 2 CTAs/SM
#define NCH1 (D_/32)           // 32

// GEMM2 (K-chunk 64, 3 stages)
#define A2_STRIDE 144          // 64 fp16 (128B) + 16B pad; 9x16B
#define A2_T 18432             // 128*144
#define B2_T 17408             // 64*272
#define G2_ST (A2_T + B2_T)    // 35840
#define G2_SMEM (3*G2_ST)      // 107520 -> 2 CTAs/SM
#define NCH2H (F_/2/64)        // 32 chunks per split-K half

__device__ __forceinline__ float silu(float g) {
    return g / (1.f + expf(-g));
}

// GEMM1: h = silu(xg @ w1) * (xg @ w3)  (M=128 pairs, N=128 of F, K=D)
// 512 threads, 4x4 warps of 32x32 warp tiles
__global__ __launch_bounds__(512)
void gemm1_mma() {
    extern __shared__ char smem[];
    int e = blockIdx.z;
    int cnt = g_counts[e];
    int m0 = blockIdx.x * 128;
    if (m0 >= cnt) return;
    int base = g_offsets[e];
    int n0 = blockIdx.y * 128;

    int tid = threadIdx.x;
    uint32_t sb = smem_u32(smem);

    int arow = tid >> 2, aq = tid & 3;
    int rcl = min(m0 + arow, cnt - 1);
    int tok = g_pair_token[base + rcl];
    const __half* asrc = g_x16 + (size_t)tok * D_ + aq * 8;
    uint32_t adst = (uint32_t)(arow * A_STRIDE + aq * 16);

    const __half* bsrc[2];
    uint32_t bdst[2];
#pragma unroll
    for (int i = 0; i < 2; i++) {
        int idx = i * 512 + tid;
        int mat = idx >> 9, rem = idx & 511;
        int krow = rem >> 4, col = rem & 15;
        bsrc[i] = (mat ? g_w3_16 : g_w1_16) + (size_t)e * D_ * F_
                  + (size_t)krow * F_ + n0 + col * 8;
        bdst[i] = (uint32_t)(A_T + mat * B_T + krow * B_STRIDE + col * 16);
    }

    auto issue = [&](int c, int slot) {
        uint32_t st = sb + slot * G1_ST;
        CP16(st + adst, asrc + c * 32);
#pragma unroll
        for (int i = 0; i < 2; i++)
            CP16(st + bdst[i], bsrc[i] + (size_t)c * 32 * F_);
    };

    int wid = tid >> 5, lane = tid & 31;
    int wm = wid & 3, wn = wid >> 2;
    int la_row = (lane & 7) + ((lane >> 3) & 1) * 8;
    int la_k   = (lane >> 4) * 8;
    uint32_t aoff = (uint32_t)((wm * 32 + la_row) * A_STRIDE + la_k * 2);
    int lb_k = (lane & 7) + ((lane >> 3) & 1) * 8;
    int lb_n = (lane >> 4) * 8;
    uint32_t boff = (uint32_t)(lb_k * B_STRIDE + (wn * 32 + lb_n) * 2);

    float acc1[2][4][4], acc3[2][4][4];
#pragma unroll
    for (int mt = 0; mt < 2; mt++)
#pragma unroll
        for (int nt = 0; nt < 4; nt++)
#pragma unroll
            for (int c = 0; c < 4; c++) { acc1[mt][nt][c] = 0.f; acc3[mt][nt][c] = 0.f; }

    auto compute = [&](int slot) {
        uint32_t stb = sb + slot * G1_ST;
#pragma unroll
        for (int ks = 0; ks < 2; ks++) {
            uint32_t Ah = stb + aoff + ks * 32;
            uint32_t Bb = stb + A_T + boff + ks * 16 * B_STRIDE;
            uint32_t a[2][4];
            LDSM4(a[0], Ah);
            LDSM4(a[1], Ah + 16 * A_STRIDE);
#pragma unroll
            for (int ng = 0; ng < 2; ng++) {
                uint32_t b1[4], b3[4];
                LDSM4T(b1, Bb + ng * 32);
                LDSM4T(b3, Bb + B_T + ng * 32);
#pragma unroll
                for (int mt = 0; mt < 2; mt++)
#pragma unroll
                    for (int j = 0; j < 2; j++) {
                        int nt = ng * 2 + j;
                        MMA(acc1[mt][nt], a[mt], b1[2 * j], b1[2 * j + 1]);
                        MMA(acc3[mt][nt], a[mt], b3[2 * j], b3[2 * j + 1]);
                    }
            }
        }
    };

#pragma unroll
    for (int s = 0; s < NSTG - 1; s++) { issue(s, s); CP_COMMIT(); }
#pragma unroll 1
    for (int c = 0; c < NCH1; c++) {
        CP_WAIT2();
        __syncthreads();
        int nc = c + NSTG - 1;
        if (nc < NCH1) issue(nc, nc & (NSTG - 1));
        CP_COMMIT();
        compute(c & (NSTG - 1));
    }

    int r0  = m0 + wm * 32 + (lane >> 2);
    int col = n0 + wn * 32 + (lane & 3) * 2;
#pragma unroll
    for (int mt = 0; mt < 2; mt++) {
#pragma unroll
        for (int half = 0; half < 2; half++) {
            int ra = r0 + mt * 16 + half * 8;
            if (ra < cnt) {
                size_t rowo = (size_t)(base + ra) * F_;
#pragma unroll
                for (int nt = 0; nt < 4; nt++) {
                    int cc = col + nt * 8;
                    float vx = silu(acc1[mt][nt][2 * half])     * acc3[mt][nt][2 * half];
                    float vy = silu(acc1[mt][nt][2 * half + 1]) * acc3[mt][nt][2 * half + 1];
                    *(uint32_t*)(g_h16 + rowo + cc) = hpack(__floats2half2_rn(vx, vy));
                }
            }
        }
    }
}

// GEMM2: out[token] += w * (h @ w2)  (M=128, N=128 of D, K=2048 per split half)
// 512 threads, 4x4 warps of 32x32 warp tiles, K-chunk=64, 3-stage ring
__global__ __launch_bounds__(512)
void gemm2_mma(float* __restrict__ out) {
    extern __shared__ char smem[];
    int e  = blockIdx.z >> 1;
    int kz = blockIdx.z & 1;
    int cnt = g_counts[e];
    int m0 = blockIdx.x * 128;
    if (m0 >= cnt) return;
    int base = g_offsets[e];
    int n0 = blockIdx.y * 128;
    int kbase = kz * (F_ / 2);

    int tid = threadIdx.x;
    uint32_t sb = smem_u32(smem);

    // A loader: 2 granules/thread: g = i*512+tid: row=g>>3 (0..127), q=g&7
    const __half* asrc[2];
    uint32_t adst[2];
#pragma unroll
    for (int i = 0; i < 2; i++) {
        int g = i * 512 + tid;
        int row = g >> 3, q = g & 7;
        int rcl = min(m0 + row, cnt - 1);
        asrc[i] = g_h16 + (size_t)(base + rcl) * F_ + kbase + q * 8;
        adst[i] = (uint32_t)(row * A2_STRIDE + q * 16);
    }

    // B loader: 2 granules/thread: g = i*512+tid: krow=g>>4 (0..63), col=g&15
    const __half* bsrc[2];
    uint32_t bdst[2];
#pragma unroll
    for (int i = 0; i < 2; i++) {
        int g = i * 512 + tid;
        int krow = g >> 4, col = g & 15;
        bsrc[i] = g_w2_16 + (size_t)e * F_ * D_
                  + (size_t)(kbase + krow) * D_ + n0 + col * 8;
        bdst[i] = (uint32_t)(A2_T + krow * B_STRIDE + col * 16);
    }

    auto issue = [&](int c, int slot) {
        uint32_t st = sb + slot * G2_ST;
#pragma unroll
        for (int i = 0; i < 2; i++)
            CP16(st + adst[i], asrc[i] + c * 64);
#pragma unroll
        for (int i = 0; i < 2; i++)
            CP16(st + bdst[i], bsrc[i] + (size_t)c * 64 * D_);
    };

    int wid = tid >> 5, lane = tid & 31;
    int wm = wid & 3, wn = wid >> 2;
    int la_row = (lane & 7) + ((lane >> 3) & 1) * 8;
    int la_k   = (lane >> 4) * 8;
    uint32_t aoff = (uint32_t)((wm * 32 + la_row) * A2_STRIDE + la_k * 2);
    int lb_k = (lane & 7) + ((lane >> 3) & 1) * 8;
    int lb_n = (lane >> 4) * 8;
    uint32_t boff = (uint32_t)(lb_k * B_STRIDE + (wn * 32 + lb_n) * 2);

    float acc[2][4][4];
#pragma unroll
    for (int mt = 0; mt < 2; mt++)
#pragma unroll
        for (int nt = 0; nt < 4; nt++)
#pragma unroll
            for (int c = 0; c < 4; c++) acc[mt][nt][c] = 0.f;

    auto compute = [&](int slot) {
        uint32_t stb = sb + slot * G2_ST;
#pragma unroll
        for (int ks = 0; ks < 4; ks++) {
            uint32_t Ah = stb + aoff + ks * 32;
            uint32_t Bb = stb + A2_T + boff + ks * 16 * B_STRIDE;
            uint32_t a[2][4];
            LDSM4(a[0], Ah);
            LDSM4(a[1], Ah + 16 * A2_STRIDE);
#pragma unroll
            for (int ng = 0; ng < 2; ng++) {
                uint32_t b[4];
                LDSM4T(b, Bb + ng * 32);
#pragma unroll
                for (int mt = 0; mt < 2; mt++)
#pragma unroll
                    for (int j = 0; j < 2; j++) {
                        int nt = ng * 2 + j;
                        MMA(acc[mt][nt], a[mt], b[2 * j], b[2 * j + 1]);
                    }
            }
        }
    };

    // 3-stage pipeline: prologue issues 0,1; steady state keeps 1 chunk ahead
    issue(0, 0); CP_COMMIT();
    issue(1, 1); CP_COMMIT();
#pragma unroll 1
    for (int c = 0; c < NCH2H; c++) {
        CP_WAIT1();
        __syncthreads();
        int nc = c + 2;
        if (nc < NCH2H) issue(nc, nc % 3);
        CP_COMMIT();
        compute(c % 3);
    }

    int r0  = m0 + wm * 32 + (lane >> 2);
    int col = n0 + wn * 32 + (lane & 3) * 2;
#pragma unroll
    for (int mt = 0; mt < 2; mt++) {
#pragma unroll
        for (int half = 0; half < 2; half++) {
            int ra = r0 + mt * 16 + half * 8;
            if (ra < cnt) {
                int p = base + ra;
                int tok = g_pair_token[p];
                float wgt = g_pair_w[p];
                float* op = out + (size_t)tok * D_;
#pragma unroll
                for (int nt = 0; nt < 4; nt++) {
                    int cc = col + nt * 8;
                    atomicAdd(op + cc,     acc[mt][nt][2 * half]     * wgt);
                    atomicAdd(op + cc + 1, acc[mt][nt][2 * half + 1] * wgt);
                }
            }
        }
    }
}

// ---------------- launch ---------------------------------------------------
static cudaStream_t g_s1 = nullptr, g_s2 = nullptr;
static cudaEvent_t  g_e0, g_e1, g_e2;

extern "C" void kernel_launch(void* const* d_in, const int* in_sizes, int n_in,
                              void* d_out, int out_size) {
    const float* x  = (const float*)d_in[0];
    const float* gw = (const float*)d_in[1];
    const float* w1 = (const float*)d_in[2];
    const float* w3 = (const float*)d_in[3];
    const float* w2 = (const float*)d_in[4];
    float* out    = (float*)d_out;
    float* out_rl = out + (size_t)T_ * D_;

    if (g_s1 == nullptr) {
        cudaStreamCreateWithFlags(&g_s1, cudaStreamNonBlocking);
        cudaStreamCreateWithFlags(&g_s2, cudaStreamNonBlocking);
        cudaEventCreateWithFlags(&g_e0, cudaEventDisableTiming);
        cudaEventCreateWithFlags(&g_e1, cudaEventDisableTiming);
        cudaEventCreateWithFlags(&g_e2, cudaEventDisableTiming);
    }

    cudaFuncSetAttribute(gemm1_mma, cudaFuncAttributeMaxDynamicSharedMemorySize, G1_SMEM);
    cudaFuncSetAttribute(gemm2_mma, cudaFuncAttributeMaxDynamicSharedMemorySize, G2_SMEM);

    __half *w1_16, *w3_16, *w2_16;
    cudaGetSymbolAddress((void**)&w1_16, g_w1_16);
    cudaGetSymbolAddress((void**)&w3_16, g_w3_16);
    cudaGetSymbolAddress((void**)&w2_16, g_w2_16);

    // fork converts onto side streams
    cudaEventRecord(g_e0, 0);
    cudaStreamWaitEvent(g_s1, g_e0, 0);
    cudaStreamWaitEvent(g_s2, g_e0, 0);
    tofp16_dual_kernel<<<dim3(8192, 2), 256, 0, g_s1>>>(
        w1, w1_16, w3, w3_16, (size_t)E_ * D_ * F_ / 4);
    cudaEventRecord(g_e1, g_s1);
    tofp16_kernel<<<8192, 256, 0, g_s2>>>(w2, w2_16, (size_t)E_ * F_ * D_ / 4);
    cudaEventRecord(g_e2, g_s2);

    // main stream: routing chain
    cudaMemsetAsync(out, 0, (size_t)out_size * sizeof(float));
    router_kernel<<<T_, 128>>>(x, gw);
    topk_kernel<<<T_ / 256, 256>>>(out_rl);
    offsets_kernel<<<1, 32>>>();
    scatter_kernel<<<T_ / 256, 256>>>();

    // join w1/w3 before GEMM1; w2 before GEMM2
    cudaStreamWaitEvent(0, g_e1, 0);
    gemm1_mma<<<dim3(32, F_ / 128, E_), 512, G1_SMEM>>>();
    cudaStreamWaitEvent(0, g_e2, 0);
    gemm2_mma<<<dim3(32, D_ / 128, E_ * 2), 512, G2_SMEM>>>(out);
}